// round 17
// baseline (speedup 1.0000x reference)
#include <cuda_runtime.h>
#include <cuda_fp16.h>

// Problem dims
#define TT 512
#define BB 256
#define SS 64
#define HH 128
#define NROW (TT*BB)          // 131072

// ---------------- scratch (device globals; no allocation allowed) ----------------
__device__ __half g_gxh[(size_t)2 * NROW * 512];     // gx fp16 (268MB)
__device__ __half g_hh [(size_t)2 * NROW * HH];      // LSTM hidden outputs fp16 (67MB)
__device__ __half g_wih16[2 * 512 * 128];            // wih packed fp16

// ---------------- helpers ----------------
__device__ __forceinline__ float tanh_t(float x) {
    float y; asm("tanh.approx.f32 %0, %1;" : "=f"(y) : "f"(x)); return y;
}
__device__ __forceinline__ float sig_t(float x) {
    return fmaf(tanh_t(x * 0.5f), 0.5f, 0.5f);
}
__device__ __forceinline__ void mma16816(float* c, const unsigned* a, const unsigned* b) {
    asm volatile(
        "mma.sync.aligned.m16n8k16.row.col.f32.f16.f16.f32 "
        "{%0,%1,%2,%3}, {%4,%5,%6,%7}, {%8,%9}, {%0,%1,%2,%3};\n"
        : "+f"(c[0]), "+f"(c[1]), "+f"(c[2]), "+f"(c[3])
        : "r"(a[0]), "r"(a[1]), "r"(a[2]), "r"(a[3]), "r"(b[0]), "r"(b[1]));
}
__device__ __forceinline__ void ldsm4(unsigned* d, const __half* p) {
    unsigned addr = (unsigned)__cvta_generic_to_shared((void*)p);
    asm volatile("ldmatrix.sync.aligned.m8n8.x4.shared.b16 {%0,%1,%2,%3}, [%4];\n"
                 : "=r"(d[0]), "=r"(d[1]), "=r"(d[2]), "=r"(d[3]) : "r"(addr));
}
__device__ __forceinline__ void ldsm2(unsigned* d, const __half* p) {
    unsigned addr = (unsigned)__cvta_generic_to_shared((void*)p);
    asm volatile("ldmatrix.sync.aligned.m8n8.x2.shared.b16 {%0,%1}, [%2];\n"
                 : "=r"(d[0]), "=r"(d[1]) : "r"(addr));
}
__device__ __forceinline__ unsigned smem_u32(const void* p) {
    return (unsigned)__cvta_generic_to_shared((void*)p);
}
__device__ __forceinline__ void cpa16(void* smem_dst, const void* gsrc) {
    unsigned s = smem_u32(smem_dst);
    asm volatile("cp.async.cg.shared.global [%0], [%1], 16;" :: "r"(s), "l"(gsrc));
}
#define CP_COMMIT asm volatile("cp.async.commit_group;" ::: "memory")
#define CP_WAIT0  asm volatile("cp.async.wait_group 0;" ::: "memory")

__device__ __forceinline__ unsigned mapa_u32(unsigned addr, unsigned rank) {
    unsigned r;
    asm("mapa.shared::cluster.u32 %0, %1, %2;" : "=r"(r) : "r"(addr), "r"(rank));
    return r;
}
__device__ __forceinline__ void mbar_wait_acq_cluster(unsigned bar, unsigned parity) {
    asm volatile(
        "{\n\t.reg .pred P;\n"
        "W_%=:\n\t"
        "mbarrier.try_wait.parity.acquire.cluster.shared::cta.b64 P, [%0], %1;\n\t"
        "@P bra.uni D_%=;\n\t"
        "bra.uni W_%=;\n\t"
        "D_%=:\n\t}"
        :: "r"(bar), "r"(parity) : "memory");
}
__device__ __forceinline__ void mbar_arrive_rel_cluster(unsigned rem_bar) {
    asm volatile("mbarrier.arrive.release.cluster.shared::cluster.b64 _, [%0];"
                 :: "r"(rem_bar) : "memory");
}
__device__ __forceinline__ void st_cluster_u32(unsigned addr, unsigned v) {
    asm volatile("st.shared::cluster.b32 [%0], %1;" :: "r"(addr), "r"(v) : "memory");
}

// ---------------- pack wih -> fp16 ----------------
__global__ void pack16_kernel(const float* __restrict__ a_wih, const float* __restrict__ c_wih) {
    int idx = blockIdx.x * blockDim.x + threadIdx.x;
    if (idx >= 2 * 65536) return;
    int net = idx >> 16, r = idx & 65535;
    g_wih16[idx] = __float2half((net ? c_wih : a_wih)[r]);
}

// =====================================================================
// Fused feature kernel (exact R8): f2 = relu(relu(X@W1.T+b1)@W2.T+b2),
// then gx = f2 @ wih.T + (bih+bhh). launch_bounds(256,2) -> 2 CTA/SM.
// =====================================================================
#define XS_STR 72
#define MH_STR 136
#define FG_BS  0
#define FG_XS  3072
#define FG_W1S 21504
#define FG_W2S 39936
#define FG_C1S 74752
#define FG_SMEM 109568

__global__ void __launch_bounds__(256, 2) fg_kernel(
    const float* __restrict__ x,
    const float* __restrict__ a_w1, const float* __restrict__ a_b1,
    const float* __restrict__ a_w2, const float* __restrict__ a_b2,
    const float* __restrict__ c_w1, const float* __restrict__ c_b1,
    const float* __restrict__ c_w2, const float* __restrict__ c_b2,
    const float* __restrict__ a_bih, const float* __restrict__ a_bhh,
    const float* __restrict__ c_bih, const float* __restrict__ c_bhh)
{
    extern __shared__ __align__(16) char smraw[];
    float*  bs1  = (float*)(smraw + FG_BS);        // 128
    float*  bs2  = bs1 + 128;                      // 128
    float*  bsum = bs2 + 128;                      // 512
    __half* Xs   = (__half*)(smraw + FG_XS);       // stride 72
    __half* W1s  = (__half*)(smraw + FG_W1S);      // stride 72
    __half* W2s  = (__half*)(smraw + FG_W2S);      // stride 136
    __half* C1s  = (__half*)(smraw + FG_C1S);      // stride 136
    __half* F2s  = (__half*)(smraw + FG_XS);       // stride 136 (overlays Xs+W1s)
    __half* Wb[2]; Wb[0] = W2s; Wb[1] = C1s;

    int tid = threadIdx.x;
    int net = blockIdx.y;
    size_t rowbase = (size_t)blockIdx.x * 128;

    const float* w1 = net ? c_w1 : a_w1;
    const float* b1 = net ? c_b1 : a_b1;
    const float* w2 = net ? c_w2 : a_w2;
    const float* b2 = net ? c_b2 : a_b2;
    const float* bih = net ? c_bih : a_bih;
    const float* bhh = net ? c_bhh : a_bhh;

    {   // X [128][64]
        const float4* xg = (const float4*)(x + rowbase * SS);
        for (int i = tid; i < 128 * 16; i += 256) {
            int r = i >> 4, c4 = i & 15;
            float4 v = xg[(size_t)r * 16 + c4];
            *(__half2*)&Xs[r * XS_STR + c4 * 4]     = __floats2half2_rn(v.x, v.y);
            *(__half2*)&Xs[r * XS_STR + c4 * 4 + 2] = __floats2half2_rn(v.z, v.w);
        }
    }
    {   // W1 [128][64]
        const float4* wg = (const float4*)w1;
        for (int i = tid; i < 128 * 16; i += 256) {
            int r = i >> 4, c4 = i & 15;
            float4 v = wg[(size_t)r * 16 + c4];
            *(__half2*)&W1s[r * XS_STR + c4 * 4]     = __floats2half2_rn(v.x, v.y);
            *(__half2*)&W1s[r * XS_STR + c4 * 4 + 2] = __floats2half2_rn(v.z, v.w);
        }
    }
    {   // W2 [128][128]
        const float4* wg = (const float4*)w2;
        for (int i = tid; i < 128 * 32; i += 256) {
            int r = i >> 5, c4 = i & 31;
            float4 v = wg[(size_t)r * 32 + c4];
            *(__half2*)&W2s[r * MH_STR + c4 * 4]     = __floats2half2_rn(v.x, v.y);
            *(__half2*)&W2s[r * MH_STR + c4 * 4 + 2] = __floats2half2_rn(v.z, v.w);
        }
    }
    if (tid < 128) { bs1[tid] = __ldg(b1 + tid); bs2[tid] = __ldg(b2 + tid); }
    for (int i = tid; i < 512; i += 256) bsum[i] = __ldg(bih + i) + __ldg(bhh + i);
    __syncthreads();

    int wid = tid >> 5, lane = tid & 31;
    int warp_m = wid & 3, warp_n = wid >> 2;
    int m_base = warp_m * 32, n_base = warp_n * 64;

    float acc[2][8][4];

    // -------- stage A: C1 = relu(X @ W1.T + b1), K=64 --------
    #pragma unroll
    for (int mt = 0; mt < 2; mt++)
        #pragma unroll
        for (int nt = 0; nt < 8; nt++)
            #pragma unroll
            for (int q = 0; q < 4; q++) acc[mt][nt][q] = 0.f;

    #pragma unroll
    for (int kt = 0; kt < 4; kt++) {
        int k0 = kt * 16;
        unsigned a[2][4], b[8][2];
        #pragma unroll
        for (int mt = 0; mt < 2; mt++) {
            int r = m_base + mt * 16 + (lane & 15);
            int c = k0 + ((lane >> 4) << 3);
            ldsm4(a[mt], Xs + r * XS_STR + c);
        }
        #pragma unroll
        for (int np = 0; np < 4; np++) {
            int n0 = n_base + np * 16;
            int rr = n0 + ((lane >> 4) << 3) + (lane & 7);
            int cc = k0 + (((lane >> 3) & 1) << 3);
            unsigned t4[4];
            ldsm4(t4, W1s + rr * XS_STR + cc);
            b[np * 2][0] = t4[0]; b[np * 2][1] = t4[1];
            b[np * 2 + 1][0] = t4[2]; b[np * 2 + 1][1] = t4[3];
        }
        #pragma unroll
        for (int mt = 0; mt < 2; mt++)
            #pragma unroll
            for (int nt = 0; nt < 8; nt++)
                mma16816(acc[mt][nt], a[mt], b[nt]);
    }
    #pragma unroll
    for (int mt = 0; mt < 2; mt++) {
        #pragma unroll
        for (int nt = 0; nt < 8; nt++) {
            int r = m_base + mt * 16 + (lane >> 2);
            int c = n_base + nt * 8 + 2 * (lane & 3);
            float v0 = fmaxf(acc[mt][nt][0] + bs1[c], 0.f);
            float v1 = fmaxf(acc[mt][nt][1] + bs1[c + 1], 0.f);
            float v2 = fmaxf(acc[mt][nt][2] + bs1[c], 0.f);
            float v3 = fmaxf(acc[mt][nt][3] + bs1[c + 1], 0.f);
            *(__half2*)&C1s[r * MH_STR + c]       = __floats2half2_rn(v0, v1);
            *(__half2*)&C1s[(r + 8) * MH_STR + c] = __floats2half2_rn(v2, v3);
        }
    }
    __syncthreads();

    // -------- stage B: F2 = relu(C1 @ W2.T + b2), K=128 --------
    #pragma unroll
    for (int mt = 0; mt < 2; mt++)
        #pragma unroll
        for (int nt = 0; nt < 8; nt++)
            #pragma unroll
            for (int q = 0; q < 4; q++) acc[mt][nt][q] = 0.f;

    #pragma unroll
    for (int kt = 0; kt < 8; kt++) {
        int k0 = kt * 16;
        unsigned a[2][4], b[8][2];
        #pragma unroll
        for (int mt = 0; mt < 2; mt++) {
            int r = m_base + mt * 16 + (lane & 15);
            int c = k0 + ((lane >> 4) << 3);
            ldsm4(a[mt], C1s + r * MH_STR + c);
        }
        #pragma unroll
        for (int np = 0; np < 4; np++) {
            int n0 = n_base + np * 16;
            int rr = n0 + ((lane >> 4) << 3) + (lane & 7);
            int cc = k0 + (((lane >> 3) & 1) << 3);
            unsigned t4[4];
            ldsm4(t4, W2s + rr * MH_STR + cc);
            b[np * 2][0] = t4[0]; b[np * 2][1] = t4[1];
            b[np * 2 + 1][0] = t4[2]; b[np * 2 + 1][1] = t4[3];
        }
        #pragma unroll
        for (int mt = 0; mt < 2; mt++)
            #pragma unroll
            for (int nt = 0; nt < 8; nt++)
                mma16816(acc[mt][nt], a[mt], b[nt]);
    }
    // epilogue B -> F2s
    #pragma unroll
    for (int mt = 0; mt < 2; mt++) {
        #pragma unroll
        for (int nt = 0; nt < 8; nt++) {
            int r = m_base + mt * 16 + (lane >> 2);
            int c = n_base + nt * 8 + 2 * (lane & 3);
            float v0 = fmaxf(acc[mt][nt][0] + bs2[c], 0.f);
            float v1 = fmaxf(acc[mt][nt][1] + bs2[c + 1], 0.f);
            float v2 = fmaxf(acc[mt][nt][2] + bs2[c], 0.f);
            float v3 = fmaxf(acc[mt][nt][3] + bs2[c + 1], 0.f);
            *(__half2*)&F2s[r * MH_STR + c]       = __floats2half2_rn(v0, v1);
            *(__half2*)&F2s[(r + 8) * MH_STR + c] = __floats2half2_rn(v2, v3);
        }
    }
    __syncthreads();

    // -------- gx phase: loop 4 weight chunks; A re-ldsm'd from F2s --------
    const __half* wsrc = g_wih16 + (size_t)net * 65536;

    for (int i = tid; i < 2048; i += 256) {
        int r = i >> 4, c = i & 15;
        cpa16(Wb[0] + r * MH_STR + c * 8, wsrc + r * 128 + c * 8);
    }
    CP_COMMIT;
    CP_WAIT0;
    __syncthreads();

    __half* outp = g_gxh + (size_t)net * NROW * 512;

    #pragma unroll
    for (int ch = 0; ch < 4; ch++) {
        if (ch < 3) {
            const __half* src = wsrc + (ch + 1) * 128 * 128;
            __half* dst = Wb[(ch + 1) & 1];
            for (int i = tid; i < 2048; i += 256) {
                int r = i >> 4, c = i & 15;
                cpa16(dst + r * MH_STR + c * 8, src + r * 128 + c * 8);
            }
            CP_COMMIT;
        }
        const __half* Ws = Wb[ch & 1];

        #pragma unroll
        for (int mt = 0; mt < 2; mt++)
            #pragma unroll
            for (int nt = 0; nt < 8; nt++)
                #pragma unroll
                for (int q = 0; q < 4; q++) acc[mt][nt][q] = 0.f;

        #pragma unroll
        for (int kt = 0; kt < 8; kt++) {
            int k0 = kt * 16;
            unsigned a[2][4], b[8][2];
            #pragma unroll
            for (int mt = 0; mt < 2; mt++) {
                int r = m_base + mt * 16 + (lane & 15);
                int c = k0 + ((lane >> 4) << 3);
                ldsm4(a[mt], F2s + r * MH_STR + c);
            }
            #pragma unroll
            for (int np = 0; np < 4; np++) {
                int n0 = n_base + np * 16;
                int rr = n0 + ((lane >> 4) << 3) + (lane & 7);
                int cc = k0 + (((lane >> 3) & 1) << 3);
                unsigned t4[4];
                ldsm4(t4, Ws + rr * MH_STR + cc);
                b[np * 2][0] = t4[0]; b[np * 2][1] = t4[1];
                b[np * 2 + 1][0] = t4[2]; b[np * 2 + 1][1] = t4[3];
            }
            #pragma unroll
            for (int mt = 0; mt < 2; mt++)
                #pragma unroll
                for (int nt = 0; nt < 8; nt++)
                    mma16816(acc[mt][nt], a[mt], b[nt]);
        }
        #pragma unroll
        for (int mt = 0; mt < 2; mt++) {
            #pragma unroll
            for (int nt = 0; nt < 8; nt++) {
                int r = m_base + mt * 16 + (lane >> 2);
                int c = n_base + nt * 8 + 2 * (lane & 3);
                int gc = ch * 128 + c;
                float v0 = acc[mt][nt][0] + bsum[gc];
                float v1 = acc[mt][nt][1] + bsum[gc + 1];
                float v2 = acc[mt][nt][2] + bsum[gc];
                float v3 = acc[mt][nt][3] + bsum[gc + 1];
                *(__half2*)(outp + (rowbase + r) * (size_t)512 + gc) = __floats2half2_rn(v0, v1);
                *(__half2*)(outp + (rowbase + r + 8) * (size_t)512 + gc) = __floats2half2_rn(v2, v3);
            }
        }
        if (ch < 3) {
            CP_WAIT0;
            __syncthreads();
        }
    }
}

// =====================================================================
// LSTM recurrence, TRANSPOSED (R15/R16) + K-SPLIT step:
// gx LDS loads and the LOCAL-half h-mma (kt tiles for this CTA's own 64
// cols, written locally last step) are hoisted ABOVE the mbarrier wait;
// only the peer-half ldsm+mma and the epilogue remain after it.
// Comm: per-thread b32 push + warp-elected release-arrive (count 8).
// smem (bytes):
//   Ws   [256][136] half  0     .. 69632
//   hbuf [2][8][136] half 69632 .. 73984
//   gxs  [2][8][264] half 73984 .. 82432
//   maskb[512] u32        82432 .. 84480
//   mbars[2] u64          84480 .. 84496
// =====================================================================
#define LW_WS  0
#define LW_HB  69632
#define LW_GX  73984
#define LW_MB  82432
#define LW_BAR 84480
#define LSTM_SMEM 84512

__global__ void __launch_bounds__(256) __cluster_dims__(2, 1, 1)
lstm_cluster_kernel(const int* __restrict__ dones,
                    const float* __restrict__ a_whh, const float* __restrict__ c_whh)
{
    extern __shared__ __align__(16) char sm[];
    __half*   Ws    = (__half*)(sm + LW_WS);
    __half*   hbuf  = (__half*)(sm + LW_HB);
    __half*   gxs   = (__half*)(sm + LW_GX);
    unsigned* maskb = (unsigned*)(sm + LW_MB);

    int tid = threadIdx.x;
    int bx  = blockIdx.x;
    int net = bx >> 6;
    int rowgroup = (bx >> 1) & 31;
    int rb = rowgroup << 3;                       // first of 8 batch rows
    unsigned rank;
    asm("mov.u32 %0, %%cluster_ctarank;" : "=r"(rank));
    unsigned peer = rank ^ 1u;
    int jbase = (int)rank * 64;
    const float* whh = net ? c_whh : a_whh;

    // ---- permuted Wp rows: m -> w=m>>5, offs=m&31, gate=offs>>3, jl=8w+(offs&7) ----
    for (int i = tid; i < 256 * 32; i += 256) {
        int m = i >> 5, c4 = i & 31;
        int w  = m >> 5;
        int offs = m & 31;
        int g  = offs >> 3;
        int jl = (w << 3) + (offs & 7);
        int orig = g * 128 + jbase + jl;
        float4 v = ((const float4*)whh)[orig * 32 + c4];
        *(__half2*)&Ws[m * 136 + c4 * 4]     = __floats2half2_rn(v.x, v.y);
        *(__half2*)&Ws[m * 136 + c4 * 4 + 2] = __floats2half2_rn(v.z, v.w);
    }
    for (int i = tid; i < 2 * 8 * 136; i += 256) hbuf[i] = __float2half(0.f);
    for (int s = tid; s < 512; s += 256) {
        unsigned b = 0;
        #pragma unroll
        for (int r = 0; r < 8; r++) b |= ((unsigned)dones[s * 256 + rb + r] & 1u) << r;
        maskb[s] = b;
    }
    const __half* gxg = g_gxh + (size_t)net * NROW * 512;
    {   // gx(0): gxs[row][seg*64+u] = gx[row][seg*128 + jbase + u]
        int row = tid >> 5, rem = tid & 31, seg = rem >> 3, q = rem & 7;
        uint4 v = *(const uint4*)(gxg + (size_t)(rb + row) * 512 + seg * 128 + jbase + q * 8);
        ((uint4*)gxs)[33 * row + 8 * seg + q] = v;
    }
    unsigned barL0 = smem_u32(sm + LW_BAR);
    unsigned barL1 = barL0 + 8;
    if (tid == 0) {
        asm volatile("mbarrier.init.shared.b64 [%0], %1;" :: "r"(barL0), "r"(8u));
        asm volatile("mbarrier.init.shared.b64 [%0], %1;" :: "r"(barL1), "r"(8u));
    }
    __syncthreads();
    asm volatile("barrier.cluster.arrive.aligned;" ::: "memory");
    asm volatile("barrier.cluster.wait.aligned;" ::: "memory");

    unsigned remBar[2];
    remBar[0] = mapa_u32(barL0, peer);
    remBar[1] = mapa_u32(barL1, peer);

    int lane = tid & 31, wid = tid >> 5;

    // hoist Wp A fragments: 2 mtiles x 8 kt x 4 regs (m rows [32w, 32w+32))
    unsigned afr[2][8][4];
    #pragma unroll
    for (int mt = 0; mt < 2; mt++)
        #pragma unroll
        for (int kt = 0; kt < 8; kt++) {
            int r = 32 * wid + mt * 16 + (lane & 15);
            int c = kt * 16 + ((lane >> 4) << 3);
            ldsm4(afr[mt][kt], Ws + r * 136 + c);
        }

    int s  = lane >> 2;            // 0..7
    int jl = 8 * wid + s;          // this thread's local hidden col
    int bA = 2 * (lane & 3);       // batch rows
    int bB = bA + 1;
    bool leftT = ((s & 1) == 0);   // pair role: left stores row bA, right row bB
    int rowSt = leftT ? bA : bB;
    int colSt = leftT ? jl : (jl - 1);   // even in both cases -> 4B aligned

    // remote b32 push addresses for both hbuf ping-pong buffers
    unsigned remH[2];
    {
        unsigned base = smem_u32(hbuf);
        #pragma unroll
        for (int buf = 0; buf < 2; buf++)
            remH[buf] = mapa_u32(base + (unsigned)(((buf * 8 + rowSt) * 136 + jbase + colSt) * 2), peer);
    }

    // k-split: own-half kt tiles cover cols [jbase, jbase+64)
    int ktOwn0  = (int)rank * 4;
    int ktPeer0 = 4 - (int)rank * 4;

    float cstA = 0.f, cstB = 0.f;
    __half* hog = g_hh + (size_t)net * NROW * HH;
    int ph0 = 0, ph1 = 0;

    for (int t = 0; t < TT; t++) {
        bool haveNext = (t < TT - 1);
        uint4 pf;
        if (haveNext) {
            int prow = tid >> 5, rem = tid & 31, seg = rem >> 3, q = rem & 7;
            pf = *(const uint4*)(gxg + (size_t)((t + 1) * 256 + rb + prow) * 512
                                 + seg * 128 + jbase + q * 8);
        }

        // ---- peer-independent work first ----
        // gx epilogue loads (gxs[t&1] written locally last step, barrier-ordered)
        const __half* gxcur = gxs + (t & 1) * 2112;
        float giA = __half2float(gxcur[bA * 264 + jl]);
        float giB = __half2float(gxcur[bB * 264 + jl]);
        float gfA = __half2float(gxcur[bA * 264 + 64 + jl]);
        float gfB = __half2float(gxcur[bB * 264 + 64 + jl]);
        float ggA = __half2float(gxcur[bA * 264 + 128 + jl]);
        float ggB = __half2float(gxcur[bB * 264 + 128 + jl]);
        float goA = __half2float(gxcur[bA * 264 + 192 + jl]);
        float goB = __half2float(gxcur[bB * 264 + 192 + jl]);

        // local-half B frags + mma (own 64 cols: written locally last step)
        const __half* hb = hbuf + (t & 1) * (8 * 136);
        float acc[2][4];
        #pragma unroll
        for (int mt = 0; mt < 2; mt++)
            #pragma unroll
            for (int q = 0; q < 4; q++) acc[mt][q] = 0.f;

        #pragma unroll
        for (int kq = 0; kq < 4; kq++) {
            int kt = ktOwn0 + kq;
            unsigned B[2];
            ldsm2(B, hb + (lane & 7) * 136 + kt * 16 + (((lane >> 3) & 1) << 3));
            mma16816(acc[0], afr[0][kt], B);
            mma16816(acc[1], afr[1][kt], B);
        }

        // ---- wait for peer's half, then finish the mma ----
        if (t > 0) {
            if ((t - 1) & 1) { mbar_wait_acq_cluster(barL1, (unsigned)ph1); ph1 ^= 1; }
            else             { mbar_wait_acq_cluster(barL0, (unsigned)ph0); ph0 ^= 1; }
        }

        #pragma unroll
        for (int kq = 0; kq < 4; kq++) {
            int kt = ktPeer0 + kq;
            unsigned B[2];
            ldsm2(B, hb + (lane & 7) * 136 + kt * 16 + (((lane >> 3) & 1) << 3));
            mma16816(acc[0], afr[0][kt], B);
            mma16816(acc[1], afr[1][kt], B);
        }
        // acc[0][0/1] = gate i (bA/bB); acc[0][2/3] = gate f;
        // acc[1][0/1] = gate g;         acc[1][2/3] = gate o.

        // ---- register epilogue (pair-shuffle b32 stores) ----
        {
            float iA = sig_t(acc[0][0] + giA), iB = sig_t(acc[0][1] + giB);
            float fA = sig_t(acc[0][2] + gfA), fB = sig_t(acc[0][3] + gfB);
            float gA = tanh_t(acc[1][0] + ggA), gB = tanh_t(acc[1][1] + ggB);
            float oA = sig_t(acc[1][2] + goA), oB = sig_t(acc[1][3] + goB);

            float c2A = fA * cstA + iA * gA;
            float c2B = fB * cstB + iB * gB;
            float h2A = oA * tanh_t(c2A);
            float h2B = oB * tanh_t(c2B);

            unsigned bits = maskb[t];
            float mA = ((bits >> bA) & 1u) ? 0.f : 1.f;
            float mB = ((bits >> bB) & 1u) ? 0.f : 1.f;
            cstA = c2A * mA;
            cstB = c2B * mB;

            // pack {rowA, rowB} halves; exchange with jl-neighbor (lane^4)
            unsigned pkm = (unsigned)__half_as_ushort(__float2half(h2A * mA))
                         | ((unsigned)__half_as_ushort(__float2half(h2B * mB)) << 16);
            unsigned pku = (unsigned)__half_as_ushort(__float2half(h2A))
                         | ((unsigned)__half_as_ushort(__float2half(h2B)) << 16);
            unsigned otm = __shfl_xor_sync(0xffffffffu, pkm, 4);
            unsigned otu = __shfl_xor_sync(0xffffffffu, pku, 4);
            // left: row bA cols {jl, jl+1}; right: row bB cols {jl-1, jl}
            unsigned vm = leftT ? ((pkm & 0xFFFFu) | (otm << 16))
                                : ((otm >> 16) | (pkm & 0xFFFF0000u));
            unsigned vu = leftT ? ((pku & 0xFFFFu) | (otu << 16))
                                : ((otu >> 16) | (pku & 0xFFFF0000u));

            if (haveNext) {
                int nb = (t + 1) & 1;
                // remote b32 push ASAP (in flight during rest of epilogue)
                st_cluster_u32(remH[nb], vm);
                // warp-level HB for all lanes' pushes, then ONE cumulative
                // release-arrive per warp (barrier count = 8)
                __syncwarp();
                if (lane == 0) mbar_arrive_rel_cluster(remBar[t & 1]);
                // local store (same layout)
                *(unsigned*)&hbuf[(nb * 8 + rowSt) * 136 + jbase + colSt] = vm;
                {
                    int prow = tid >> 5, rem = tid & 31, seg = rem >> 3, q = rem & 7;
                    ((uint4*)(gxs + nb * 2112))[33 * prow + 8 * seg + q] = pf;
                }
            }
            *(unsigned*)(hog + (size_t)(t * 256 + rb + rowSt) * HH + jbase + colSt) = vu;
        }
        __syncthreads();
    }

    asm volatile("barrier.cluster.arrive.aligned;" ::: "memory");
    asm volatile("barrier.cluster.wait.aligned;" ::: "memory");
}

// =====================================================================
// Heads on HMMA (exact R8)
// =====================================================================
#define HD_HA 0
#define HD_HC 34816
#define HD_W  69632
#define HD_B  78336
#define HD_SMEM 78464

__global__ void __launch_bounds__(256) heads_mma_kernel(
    const float* __restrict__ mw, const float* __restrict__ mb,
    const float* __restrict__ lw, const float* __restrict__ lb,
    const float* __restrict__ vw, const float* __restrict__ vb,
    float* __restrict__ out)
{
    extern __shared__ __align__(16) char sm[];
    __half* Ha = (__half*)(sm + HD_HA);   // [128][136]
    __half* Hc = (__half*)(sm + HD_HC);   // [128][136]
    __half* Wh = (__half*)(sm + HD_W);    // [32][136]
    float*  bsm = (float*)(sm + HD_B);

    int tid = threadIdx.x;
    size_t rowbase = (size_t)blockIdx.x * 128;

    const __half* ha = g_hh + rowbase * HH;
    const __half* hc = g_hh + (size_t)NROW * HH + rowbase * HH;
    for (int i = tid; i < 2048; i += 256) {
        int r = i >> 4, c = i & 15;
        cpa16(Ha + r * 136 + c * 8, ha + (size_t)r * HH + c * 8);
        cpa16(Hc + r * 136 + c * 8, hc + (size_t)r * HH + c * 8);
    }
    CP_COMMIT;
    for (int i = tid; i < 4096; i += 256) {
        int r = i >> 7, c = i & 127;
        float v = 0.f;
        if (r < 8) v = mw[r * 128 + c];
        else if (r < 16) v = lw[(r - 8) * 128 + c];
        else if (r == 16) v = vw[c];
        Wh[r * 136 + c] = __float2half(v);
    }
    if (tid < 8) { bsm[tid] = mb[tid]; bsm[8 + tid] = lb[tid]; }
    if (tid == 16) bsm[16] = vb[0];
    CP_WAIT0;
    __syncthreads();

    int wid = tid >> 5, lane = tid & 31;
    int r0 = wid * 16;

    unsigned bf[8][3][2];
    #pragma unroll
    for (int kt = 0; kt < 8; kt++) {
        int k0 = kt * 16;
        {
            int rr = ((lane >> 4) << 3) + (lane & 7);
            int cc = k0 + (((lane >> 3) & 1) << 3);
            unsigned t4[4];
            ldsm4(t4, Wh + rr * 136 + cc);
            bf[kt][0][0] = t4[0]; bf[kt][0][1] = t4[1];
            bf[kt][1][0] = t4[2]; bf[kt][1][1] = t4[3];
        }
        {
            int rr = 16 + ((lane >> 4) << 3) + (lane & 7);
            int cc = k0 + (((lane >> 3) & 1) << 3);
            unsigned t4[4];
            ldsm4(t4, Wh + rr * 136 + cc);
            bf[kt][2][0] = t4[0]; bf[kt][2][1] = t4[1];
        }
    }

    float accM[4], accL[4], accV[4];
    #pragma unroll
    for (int q = 0; q < 4; q++) { accM[q] = 0.f; accL[q] = 0.f; accV[q] = 0.f; }

    #pragma unroll
    for (int kt = 0; kt < 8; kt++) {
        int k0 = kt * 16;
        unsigned a[4], cfr[4];
        ldsm4(a,   Ha + (r0 + (lane & 15)) * 136 + k0 + ((lane >> 4) << 3));
        ldsm4(cfr, Hc + (r0 + (lane & 15)) * 136 + k0 + ((lane >> 4) << 3));
        mma16816(accM, a, bf[kt][0]);
        mma16816(accL, a, bf[kt][1]);
        mma16816(accV, cfr, bf[kt][2]);
    }

    int row = lane >> 2, c0 = 2 * (lane & 3);
    size_t gr0 = rowbase + r0 + row;
    size_t gr1 = gr0 + 8;
    *(float2*)(out + gr0 * 8 + c0) = make_float2(accM[0] + bsm[c0], accM[1] + bsm[c0 + 1]);
    *(float2*)(out + gr1 * 8 + c0) = make_float2(accM[2] + bsm[c0], accM[3] + bsm[c0 + 1]);
    float* outs = out + (size_t)NROW * 8;
    *(float2*)(outs + gr0 * 8 + c0) =
        make_float2(__expf(accL[0] + bsm[8 + c0]), __expf(accL[1] + bsm[8 + c0 + 1]));
    *(float2*)(outs + gr1 * 8 + c0) =
        make_float2(__expf(accL[2] + bsm[8 + c0]), __expf(accL[3] + bsm[8 + c0 + 1]));
    if ((lane & 3) == 0) {
        float* outv = out + (size_t)NROW * 16;
        outv[gr0] = accV[0] + bsm[16];
        outv[gr1] = accV[2] + bsm[16];
    }
}

// ---------------- launch ----------------
extern "C" void kernel_launch(void* const* d_in, const int* in_sizes, int n_in,
                              void* d_out, int out_size)
{
    const float* state  = (const float*)d_in[0];
    const int*   dones  = (const int*)d_in[1];
    const float* a_w1   = (const float*)d_in[2];
    const float* a_b1   = (const float*)d_in[3];
    const float* a_w2   = (const float*)d_in[4];
    const float* a_b2   = (const float*)d_in[5];
    const float* c_w1   = (const float*)d_in[6];
    const float* c_b1   = (const float*)d_in[7];
    const float* c_w2   = (const float*)d_in[8];
    const float* c_b2   = (const float*)d_in[9];
    const float* a_wih  = (const float*)d_in[10];
    const float* a_whh  = (const float*)d_in[11];
    const float* a_bih  = (const float*)d_in[12];
    const float* a_bhh  = (const float*)d_in[13];
    const float* c_wih  = (const float*)d_in[14];
    const float* c_whh  = (const float*)d_in[15];
    const float* c_bih  = (const float*)d_in[16];
    const float* c_bhh  = (const float*)d_in[17];
    const float* mean_w = (const float*)d_in[18];
    const float* mean_b = (const float*)d_in[19];
    const float* lstd_w = (const float*)d_in[20];
    const float* lstd_b = (const float*)d_in[21];
    const float* val_w  = (const float*)d_in[22];
    const float* val_b  = (const float*)d_in[23];

    cudaFuncSetAttribute(fg_kernel, cudaFuncAttributeMaxDynamicSharedMemorySize, FG_SMEM);
    cudaFuncSetAttribute(lstm_cluster_kernel, cudaFuncAttributeMaxDynamicSharedMemorySize, LSTM_SMEM);
    cudaFuncSetAttribute(heads_mma_kernel, cudaFuncAttributeMaxDynamicSharedMemorySize, HD_SMEM);

    pack16_kernel<<<512, 256>>>(a_wih, c_wih);

    dim3 fgg(1024, 2);
    fg_kernel<<<fgg, 256, FG_SMEM>>>(state,
                                     a_w1, a_b1, a_w2, a_b2,
                                     c_w1, c_b1, c_w2, c_b2,
                                     a_bih, a_bhh, c_bih, c_bhh);

    lstm_cluster_kernel<<<128, 256, LSTM_SMEM>>>(dones, a_whh, c_whh);

    heads_mma_kernel<<<1024, 256, HD_SMEM>>>(mean_w, mean_b, lstd_w, lstd_b,
                                             val_w, val_b, (float*)d_out);
}